// round 12
// baseline (speedup 1.0000x reference)
#include <cuda_runtime.h>
#include <cuda_fp16.h>
#include <cuda_bf16.h>

// Problem shape (fixed by dataset):
//   h: [N=200000, D=128] fp32
//   pos_src/pos_dst: [262144] int32
//   neg_src/neg_dst: [1048576] int32   (num_negs = 4, contiguous per pos edge)
//   out: [2] fp32  -> (loss, mrr)

#define DIM 128
#define N_NODES 200000

// Scratch (allocation-free rule: __device__ globals)
__device__ __half   g_h_half[(size_t)N_NODES * DIM];   // 51.2 MB fp16 copy of h
__device__ double   g_loss_sum;
__device__ double   g_mrr_sum;
__device__ unsigned g_done;

// Streaming fp32 -> fp16 conversion of h; block 0 also resets accumulators.
__global__ __launch_bounds__(256) void convert_kernel(
    const float* __restrict__ h, long long n_elems)
{
    if (blockIdx.x == 0 && threadIdx.x == 0) {
        g_loss_sum = 0.0;
        g_mrr_sum  = 0.0;
        g_done     = 0u;
    }
    const long long n8 = n_elems >> 3;
    const long long stride = (long long)gridDim.x * blockDim.x;
    for (long long i = (long long)blockIdx.x * blockDim.x + threadIdx.x;
         i < n8; i += stride) {
        const float4* src = reinterpret_cast<const float4*>(h) + i * 2;
        float4 f0 = src[0];
        float4 f1 = src[1];
        __half2 o[4];
        o[0] = __floats2half2_rn(f0.x, f0.y);
        o[1] = __floats2half2_rn(f0.z, f0.w);
        o[2] = __floats2half2_rn(f1.x, f1.y);
        o[3] = __floats2half2_rn(f1.z, f1.w);
        reinterpret_cast<float4*>(g_h_half)[i] = *reinterpret_cast<float4*>(o);
    }
}

// 16-element partial dot: two depth-4 HFMA2 chains + one HADD2, single
// fp32 conversion at the end.
__device__ __forceinline__ float dot16_chain(uint4 a0, uint4 b0,
                                             uint4 a1, uint4 b1) {
    const __half2* A0 = reinterpret_cast<const __half2*>(&a0);
    const __half2* B0 = reinterpret_cast<const __half2*>(&b0);
    const __half2* A1 = reinterpret_cast<const __half2*>(&a1);
    const __half2* B1 = reinterpret_cast<const __half2*>(&b1);
    __half2 acc0 = __hmul2(A0[0], B0[0]);
    __half2 acc1 = __hmul2(A1[0], B1[0]);
    #pragma unroll
    for (int k = 1; k < 4; k++) {
        acc0 = __hfma2(A0[k], B0[k], acc0);
        acc1 = __hfma2(A1[k], B1[k], acc1);
    }
    float2 f = __half22float2(__hadd2(acc0, acc1));
    return f.x + f.y;
}

// Per-thread partial dot for an 8-lane edge group. Lane `sub` (0..7) reads
// float4-sized chunks {sub, sub+8} of both 256B rows -> 8 consecutive lanes
// cover a full 128B line per LDG wavefront. No shuffles here.
__device__ __forceinline__ float partial_dot(int src, int dst, int sub) {
    const uint4* __restrict__ a =
        reinterpret_cast<const uint4*>(g_h_half + (size_t)src * DIM);
    const uint4* __restrict__ b =
        reinterpret_cast<const uint4*>(g_h_half + (size_t)dst * DIM);
    uint4 a0 = a[sub];     uint4 b0 = b[sub];
    uint4 a1 = a[sub + 8]; uint4 b1 = b[sub + 8];
    return dot16_chain(a0, b0, a1, b1);
}

// Fused SDDMM + BCE loss + MRR. One 8-thread group owns pos edge i and its
// 4 negatives (neg indices 4i..4i+3).
// - Indices for iteration i+1 are prefetched during iteration i (hides the
//   index-load leg of the latency chain).
// - After the butterfly every lane holds t0..t4; lane k (k<5) evaluates the
//   softplus of t_k and accumulates into its own lacc (summed at block end),
//   so the tail is ~1 softplus deep instead of 5.
__global__ __launch_bounds__(128, 11) void fused_kernel(
    const int* __restrict__ pos_src,
    const int* __restrict__ pos_dst,
    const int* __restrict__ neg_src,
    const int* __restrict__ neg_dst,
    float* __restrict__ out,
    int e_pos, int total_edges)
{
    const int sub = threadIdx.x & 7;               // 0..7 within edge-group
    const int groups_per_block = blockDim.x >> 3;  // 16
    const int gstride = gridDim.x * groups_per_block;

    float lacc = 0.0f;
    float macc = 0.0f;

    int i = blockIdx.x * groups_per_block + (threadIdx.x >> 3);

    int psrc = 0, pdst = 0;
    int4 ns = make_int4(0, 0, 0, 0), nd = make_int4(0, 0, 0, 0);
    if (i < e_pos) {
        psrc = pos_src[i];
        pdst = pos_dst[i];
        ns = reinterpret_cast<const int4*>(neg_src)[i];
        nd = reinterpret_cast<const int4*>(neg_dst)[i];
    }

    while (i < e_pos) {
        const int inext = i + gstride;

        // 5 partial dots using the already-resident indices; the 10 gather
        // loads issue immediately at loop top.
        float t0 = partial_dot(psrc, pdst, sub);
        float t1 = partial_dot(ns.x, nd.x, sub);
        float t2 = partial_dot(ns.y, nd.y, sub);
        float t3 = partial_dot(ns.z, nd.z, sub);
        float t4 = partial_dot(ns.w, nd.w, sub);

        // Prefetch next iteration's indices (independent -> overlaps with
        // the dequant math and shuffles below).
        if (inext < e_pos) {
            psrc = pos_src[inext];
            pdst = pos_dst[inext];
            ns = reinterpret_cast<const int4*>(neg_src)[inext];
            nd = reinterpret_cast<const int4*>(neg_dst)[inext];
        }

        // Butterfly across the 8-lane group: every lane ends with full sums.
        #pragma unroll
        for (int off = 4; off; off >>= 1) {
            t0 += __shfl_xor_sync(0xffffffffu, t0, off);
            t1 += __shfl_xor_sync(0xffffffffu, t1, off);
            t2 += __shfl_xor_sync(0xffffffffu, t2, off);
            t3 += __shfl_xor_sync(0xffffffffu, t3, off);
            t4 += __shfl_xor_sync(0xffffffffu, t4, off);
        }

        // Distributed loss tail: lane k handles score t_k (k = 0..4).
        // pos (k=0): softplus(t0) - t0 = softplus(-t0); neg: softplus(t_k).
        float v = t1;
        v = (sub == 2) ? t2 : v;
        v = (sub == 3) ? t3 : v;
        v = (sub >= 4) ? t4 : v;
        v = (sub == 0) ? t0 : v;
        const float arg  = (sub == 0) ? -v : v;
        const float term = log1pf(expf(-fabsf(v))) + fmaxf(arg, 0.0f);
        if (sub < 5) lacc += term;

        // Rank on lane 0: stable argsort => rank = 1 + #{neg > pos}
        if (sub == 0) {
            int rank = 1;
            rank += (t1 > t0);
            rank += (t2 > t0);
            rank += (t3 > t0);
            rank += (t4 > t0);
            macc += 1.0f / (float)rank;
        }

        i = inext;
    }

    // Block reduction (promote to double; one value per thread)
    double dl = (double)lacc;
    double dm = (double)macc;
    #pragma unroll
    for (int off = 16; off; off >>= 1) {
        dl += __shfl_xor_sync(0xffffffffu, dl, off);
        dm += __shfl_xor_sync(0xffffffffu, dm, off);
    }
    __shared__ double wl[4], wm[4];
    if ((threadIdx.x & 31) == 0) {
        wl[threadIdx.x >> 5] = dl;
        wm[threadIdx.x >> 5] = dm;
    }
    __syncthreads();
    if (threadIdx.x == 0) {
        double sl = 0.0, sm = 0.0;
        const int nw = blockDim.x >> 5;
        for (int k = 0; k < nw; k++) { sl += wl[k]; sm += wm[k]; }
        atomicAdd(&g_loss_sum, sl);
        atomicAdd(&g_mrr_sum,  sm);
        __threadfence();
        unsigned t = atomicAdd(&g_done, 1u);
        if (t == gridDim.x - 1) {
            out[0] = (float)(g_loss_sum / (double)total_edges);
            out[1] = (float)(g_mrr_sum  / (double)e_pos);
        }
    }
}

extern "C" void kernel_launch(void* const* d_in, const int* in_sizes, int n_in,
                              void* d_out, int out_size) {
    const float* h       = (const float*)d_in[0];
    const int*   pos_src = (const int*)d_in[1];
    const int*   pos_dst = (const int*)d_in[2];
    const int*   neg_src = (const int*)d_in[3];
    const int*   neg_dst = (const int*)d_in[4];

    const long long n_h  = in_sizes[0];
    const int e_pos = in_sizes[1];
    const int e_neg = in_sizes[3];
    const int total = e_pos + e_neg;

    float* out = (float*)d_out;

    // Convert: persistent streaming pass (HBM-bound, ~19 us floor)
    convert_kernel<<<148 * 8, 256>>>(h, n_h);

    // Fused pass: 11 blocks/SM (46-reg budget for index prefetch), 44 warps/SM.
    // 1628 blocks x 16 groups = 26048 slots, ~10 iters/slot grid-stride.
    fused_kernel<<<148 * 11, 128>>>(pos_src, pos_dst, neg_src, neg_dst,
                                    out, e_pos, total);
}

// round 14
// speedup vs baseline: 1.2077x; 1.2077x over previous
#include <cuda_runtime.h>
#include <cuda_fp16.h>
#include <cuda_bf16.h>

// Problem shape (fixed by dataset):
//   h: [N=200000, D=128] fp32
//   pos_src/pos_dst: [262144] int32
//   neg_src/neg_dst: [1048576] int32   (num_negs = 4, contiguous per pos edge)
//   out: [2] fp32  -> (loss, mrr)

#define DIM 128
#define N_NODES 200000
#define ROW_U4 (DIM / 16)   // 8 uint4 per int8 row

// Scratch (allocation-free rule: __device__ globals)
__device__ unsigned char g_h_q[(size_t)N_NODES * DIM];  // 25.6 MB int8 table
__device__ float         g_scale[N_NODES];              // per-row dequant scale
__device__ double        g_loss_sum;
__device__ double        g_mrr_sum;
__device__ unsigned      g_done;

// Per-row int8 quantization: one warp per row (32 lanes x 4 floats = 128).
// q = round(x * 127/max|row|); scale = max|row|/127. Block 0 resets accums.
__global__ __launch_bounds__(256) void quant_kernel(
    const float* __restrict__ h, int n_rows)
{
    if (blockIdx.x == 0 && threadIdx.x == 0) {
        g_loss_sum = 0.0;
        g_mrr_sum  = 0.0;
        g_done     = 0u;
    }
    const int lane   = threadIdx.x & 31;
    const int warp   = (blockIdx.x * blockDim.x + threadIdx.x) >> 5;
    const int nwarps = (gridDim.x * blockDim.x) >> 5;

    for (int r = warp; r < n_rows; r += nwarps) {
        const float4 v =
            reinterpret_cast<const float4*>(h + (size_t)r * DIM)[lane];
        float m = fmaxf(fmaxf(fabsf(v.x), fabsf(v.y)),
                        fmaxf(fabsf(v.z), fabsf(v.w)));
        #pragma unroll
        for (int off = 16; off; off >>= 1)
            m = fmaxf(m, __shfl_xor_sync(0xffffffffu, m, off));

        const float inv = (m > 0.0f) ? (127.0f / m) : 0.0f;
        int q0 = __float2int_rn(v.x * inv);
        int q1 = __float2int_rn(v.y * inv);
        int q2 = __float2int_rn(v.z * inv);
        int q3 = __float2int_rn(v.w * inv);
        unsigned packed = (unsigned)(q0 & 0xFF)
                        | ((unsigned)(q1 & 0xFF) << 8)
                        | ((unsigned)(q2 & 0xFF) << 16)
                        | ((unsigned)(q3 & 0xFF) << 24);
        reinterpret_cast<unsigned*>(g_h_q + (size_t)r * DIM)[lane] = packed;
        if (lane == 0)
            g_scale[r] = (m > 0.0f) ? (m / 127.0f) : 0.0f;
    }
}

// 16-element int8 dot via 4 exact DP4A ops.
__device__ __forceinline__ int dp16(uint4 a, uint4 b) {
    int s = 0;
    s = __dp4a((int)a.x, (int)b.x, s);
    s = __dp4a((int)a.y, (int)b.y, s);
    s = __dp4a((int)a.z, (int)b.z, s);
    s = __dp4a((int)a.w, (int)b.w, s);
    return s;
}

// Fused SDDMM + BCE loss + MRR on the int8 table.
// 8-thread group per pos edge + its 4 negatives. Per edge each lane loads ONE
// uint4 of each row (16 int8) -> only 10 uint4 (40 regs) in flight for the
// whole 5-edge burst, so all gathers issue in one batch (single latency
// exposure per iteration). Integer butterfly is exact; scores materialize
// per-lane (lane k owns edge k); rank via ballot.
__global__ __launch_bounds__(128, 9) void fused_kernel(
    const int* __restrict__ pos_src,
    const int* __restrict__ pos_dst,
    const int* __restrict__ neg_src,
    const int* __restrict__ neg_dst,
    float* __restrict__ out,
    int e_pos, int total_edges)
{
    const int lane = threadIdx.x & 31;
    const int sub  = lane & 7;                    // 0..7 within edge-group
    const int gbase = lane & ~7;                  // group base lane in warp
    const int groups_per_block = blockDim.x >> 3; // 16
    const int gstride = gridDim.x * groups_per_block;

    const uint4* __restrict__ A = reinterpret_cast<const uint4*>(g_h_q);

    float lacc = 0.0f;
    float macc = 0.0f;

    int i = blockIdx.x * groups_per_block + (threadIdx.x >> 3);

    int psrc = 0, pdst = 0;
    int4 ns = make_int4(0, 0, 0, 0), nd = make_int4(0, 0, 0, 0);
    if (i < e_pos) {
        psrc = pos_src[i];
        pdst = pos_dst[i];
        ns = reinterpret_cast<const int4*>(neg_src)[i];
        nd = reinterpret_cast<const int4*>(neg_dst)[i];
    }

    while (i < e_pos) {
        const int inext = i + gstride;

        // ---- 10 gather loads, all independent, one batch ----
        uint4 a0 = A[psrc * ROW_U4 + sub]; uint4 b0 = A[pdst * ROW_U4 + sub];
        uint4 a1 = A[ns.x * ROW_U4 + sub]; uint4 b1 = A[nd.x * ROW_U4 + sub];
        uint4 a2 = A[ns.y * ROW_U4 + sub]; uint4 b2 = A[nd.y * ROW_U4 + sub];
        uint4 a3 = A[ns.z * ROW_U4 + sub]; uint4 b3 = A[nd.z * ROW_U4 + sub];
        uint4 a4 = A[ns.w * ROW_U4 + sub]; uint4 b4 = A[nd.w * ROW_U4 + sub];

        // ---- per-lane scale fetch: lane k owns edge k (k<5) ----
        int ssrc = psrc, sdst = pdst;
        if (sub == 1) { ssrc = ns.x; sdst = nd.x; }
        if (sub == 2) { ssrc = ns.y; sdst = nd.y; }
        if (sub == 3) { ssrc = ns.z; sdst = nd.z; }
        if (sub == 4) { ssrc = ns.w; sdst = nd.w; }
        const float sab = g_scale[ssrc] * g_scale[sdst];

        // ---- prefetch next iteration's indices ----
        if (inext < e_pos) {
            psrc = pos_src[inext];
            pdst = pos_dst[inext];
            ns = reinterpret_cast<const int4*>(neg_src)[inext];
            nd = reinterpret_cast<const int4*>(neg_dst)[inext];
        }

        // ---- exact integer partial dots ----
        int t0 = dp16(a0, b0);
        int t1 = dp16(a1, b1);
        int t2 = dp16(a2, b2);
        int t3 = dp16(a3, b3);
        int t4 = dp16(a4, b4);

        // ---- integer butterfly across the 8-lane group (exact) ----
        #pragma unroll
        for (int off = 4; off; off >>= 1) {
            t0 += __shfl_xor_sync(0xffffffffu, t0, off);
            t1 += __shfl_xor_sync(0xffffffffu, t1, off);
            t2 += __shfl_xor_sync(0xffffffffu, t2, off);
            t3 += __shfl_xor_sync(0xffffffffu, t3, off);
            t4 += __shfl_xor_sync(0xffffffffu, t4, off);
        }

        // ---- per-lane score (lane k = edge k), dequantized once ----
        int myi = t1;
        myi = (sub == 2) ? t2 : myi;
        myi = (sub == 3) ? t3 : myi;
        myi = (sub >= 4) ? t4 : myi;
        myi = (sub == 0) ? t0 : myi;
        const float score = (float)myi * sab;

        // Broadcast the positive score from the group's lane 0.
        const float p = __shfl_sync(0xffffffffu, score, gbase);

        // Loss: pos (k=0): softplus(-p); neg (k=1..4): softplus(score).
        const float arg  = (sub == 0) ? -score : score;
        const float term = log1pf(expf(-fabsf(score))) + fmaxf(arg, 0.0f);
        if (sub < 5) lacc += term;

        // Rank: stable argsort => rank = 1 + #{neg > pos}, via ballot.
        const unsigned gt = __ballot_sync(
            0xffffffffu, (sub >= 1) && (sub <= 4) && (score > p));
        if (sub == 0) {
            const int rank = 1 + __popc((gt >> gbase) & 0x1Eu);
            macc += 1.0f / (float)rank;
        }

        i = inext;
    }

    // Block reduction (promote to double; one value per thread)
    double dl = (double)lacc;
    double dm = (double)macc;
    #pragma unroll
    for (int off = 16; off; off >>= 1) {
        dl += __shfl_xor_sync(0xffffffffu, dl, off);
        dm += __shfl_xor_sync(0xffffffffu, dm, off);
    }
    __shared__ double wl[4], wm[4];
    if (lane == 0) {
        wl[threadIdx.x >> 5] = dl;
        wm[threadIdx.x >> 5] = dm;
    }
    __syncthreads();
    if (threadIdx.x == 0) {
        double sl = 0.0, sm = 0.0;
        const int nw = blockDim.x >> 5;
        for (int k = 0; k < nw; k++) { sl += wl[k]; sm += wm[k]; }
        atomicAdd(&g_loss_sum, sl);
        atomicAdd(&g_mrr_sum,  sm);
        __threadfence();
        unsigned t = atomicAdd(&g_done, 1u);
        if (t == gridDim.x - 1) {
            out[0] = (float)(g_loss_sum / (double)total_edges);
            out[1] = (float)(g_mrr_sum  / (double)e_pos);
        }
    }
}

extern "C" void kernel_launch(void* const* d_in, const int* in_sizes, int n_in,
                              void* d_out, int out_size) {
    const float* h       = (const float*)d_in[0];
    const int*   pos_src = (const int*)d_in[1];
    const int*   pos_dst = (const int*)d_in[2];
    const int*   neg_src = (const int*)d_in[3];
    const int*   neg_dst = (const int*)d_in[4];

    const int n_rows = in_sizes[0] / DIM;
    const int e_pos  = in_sizes[1];
    const int e_neg  = in_sizes[3];
    const int total  = e_pos + e_neg;

    float* out = (float*)d_out;

    // Quantize: streaming pass, warp per row (~16 us, HBM-bound)
    quant_kernel<<<148 * 8, 256>>>(h, n_rows);

    // Fused pass: 9 blocks/SM (56-reg budget for the one-batch gather burst),
    // 1332 blocks x 16 groups = 21312 slots, ~12.3 iters/slot grid-stride.
    fused_kernel<<<148 * 9, 128>>>(pos_src, pos_dst, neg_src, neg_dst,
                                   out, e_pos, total);
}